// round 3
// baseline (speedup 1.0000x reference)
#include <cuda_runtime.h>
#include <cstdint>
#include <cstddef>

#define B_  16
#define S_  2048
#define H_  1024

// Scratch (static device memory — no allocation).
__device__ float g_u[B_ * H_];        // hid_part + bias, per (b, n)
__device__ float g_logits[B_ * S_];   // attention logits before softmax

// ---------------------------------------------------------------------------
// Helpers
// ---------------------------------------------------------------------------
__device__ __forceinline__ uint32_t f2tf32(float x) {
    uint32_t r;
    asm("cvt.rna.tf32.f32 %0, %1;" : "=r"(r) : "f"(x));
    return r;
}

__device__ __forceinline__ void mma_m16n8k8(float* c, const uint32_t* a,
                                            uint32_t b0, uint32_t b1) {
    asm volatile(
        "mma.sync.aligned.m16n8k8.row.col.f32.tf32.tf32.f32 "
        "{%0,%1,%2,%3}, {%4,%5,%6,%7}, {%8,%9}, {%0,%1,%2,%3};\n"
        : "+f"(c[0]), "+f"(c[1]), "+f"(c[2]), "+f"(c[3])
        : "r"(a[0]), "r"(a[1]), "r"(a[2]), "r"(a[3]), "r"(b0), "r"(b1));
}

// ---------------------------------------------------------------------------
// Kernel 1: u[b][n] = sum_k hidden[b][k] * W_attn[k][n] + b_attn[n]
// grid (16, 4), 256 threads; thread owns one n.
// ---------------------------------------------------------------------------
__global__ void u_kernel(const float* __restrict__ hidden,
                         const float* __restrict__ W,
                         const float* __restrict__ bias) {
    int b = blockIdx.x;
    int n = blockIdx.y * 256 + threadIdx.x;
    const float* h = hidden + b * H_;
    float acc = 0.f;
#pragma unroll 8
    for (int k = 0; k < H_; k++)
        acc = fmaf(h[k], W[(size_t)k * H_ + n], acc);
    g_u[b * H_ + n] = acc + bias[n];
}

// ---------------------------------------------------------------------------
// Kernel 2: fused enc@W2 (tf32 MMA) + tanh(.+u) + dot(v) -> logits
// Tile: M=128 rows of flattened (b*S+s), N-chunks of 128 over H, K=1024.
// 256 threads = 8 warps in a 4(m) x 2(n) grid; warp tile 32x64.
// ---------------------------------------------------------------------------
#define KB 16
#define MT 128
#define NT 128
#define AS_STRIDE 20    // KB + 4  -> conflict-free A frag reads
#define BS_STRIDE 136   // NT + 8  -> conflict-free B frag reads

__global__ __launch_bounds__(256, 2)
void fused_kernel(const float* __restrict__ enc,
                  const float* __restrict__ Wfull,
                  const float* __restrict__ v) {
    const float* W2 = Wfull + (size_t)H_ * H_;

    __shared__ uint32_t As[2][MT * AS_STRIDE];  // 20 KB
    __shared__ uint32_t Bs[2][KB * BS_STRIDE];  // 17 KB
    __shared__ float u_s[NT];
    __shared__ float v_s[NT];
    __shared__ float row_acc[MT];

    const int tid  = threadIdx.x;
    const int lane = tid & 31;
    const int wid  = tid >> 5;
    const int warp_m = wid & 3;   // 0..3 -> 32-row slab
    const int warp_n = wid >> 2;  // 0..1 -> 64-col slab
    const int gr0 = blockIdx.x * MT;        // global row base (b*S + s)
    const int b   = gr0 >> 11;              // S = 2048

    if (tid < MT) row_acc[tid] = 0.f;

    // Global->smem load mapping (float4 granularity).
    // A tile: 128 rows x 16 cols = 512 float4; thread does f = tid, tid+256.
    const int a_row0 = tid >> 2;            // f>>2
    const int a_c4   = tid & 3;             // f&3 (same for both)
    const int a_row1 = a_row0 + 64;
    // B tile: 16 rows x 128 cols = 512 float4.
    const int b_row0 = tid >> 5;
    const int b_c4   = tid & 31;
    const int b_row1 = b_row0 + 8;

    const float* Abase0 = enc + (size_t)(gr0 + a_row0) * H_ + a_c4 * 4;
    const float* Abase1 = enc + (size_t)(gr0 + a_row1) * H_ + a_c4 * 4;

    const int rbase = warp_m * 32 + (lane >> 2);  // C-frag row (mf=0, half 0)
    const int kq    = lane & 3;
    const int nb    = warp_n * 64 + (lane >> 2);  // B-frag col base

    for (int n0 = 0; n0 < H_; n0 += NT) {
        // Stage u, v for this N-chunk.
        if (tid < NT)            u_s[tid]       = g_u[b * H_ + n0 + tid];
        else if (tid < 2 * NT)   v_s[tid - NT]  = v[n0 + tid - NT];

        float acc[2][8][4];
#pragma unroll
        for (int mf = 0; mf < 2; mf++)
#pragma unroll
            for (int nf = 0; nf < 8; nf++)
#pragma unroll
                for (int i = 0; i < 4; i++) acc[mf][nf][i] = 0.f;

        // Preload k-block 0 into buffer 0.
        {
            float4 ar0 = *(const float4*)(Abase0);
            float4 ar1 = *(const float4*)(Abase1);
            float4 br0 = *(const float4*)(W2 + (size_t)b_row0 * H_ + n0 + b_c4 * 4);
            float4 br1 = *(const float4*)(W2 + (size_t)b_row1 * H_ + n0 + b_c4 * 4);
            uint32_t* pa0 = &As[0][a_row0 * AS_STRIDE + a_c4 * 4];
            pa0[0] = f2tf32(ar0.x); pa0[1] = f2tf32(ar0.y);
            pa0[2] = f2tf32(ar0.z); pa0[3] = f2tf32(ar0.w);
            uint32_t* pa1 = &As[0][a_row1 * AS_STRIDE + a_c4 * 4];
            pa1[0] = f2tf32(ar1.x); pa1[1] = f2tf32(ar1.y);
            pa1[2] = f2tf32(ar1.z); pa1[3] = f2tf32(ar1.w);
            uint32_t* pb0 = &Bs[0][b_row0 * BS_STRIDE + b_c4 * 4];
            pb0[0] = f2tf32(br0.x); pb0[1] = f2tf32(br0.y);
            pb0[2] = f2tf32(br0.z); pb0[3] = f2tf32(br0.w);
            uint32_t* pb1 = &Bs[0][b_row1 * BS_STRIDE + b_c4 * 4];
            pb1[0] = f2tf32(br1.x); pb1[1] = f2tf32(br1.y);
            pb1[2] = f2tf32(br1.z); pb1[3] = f2tf32(br1.w);
        }
        __syncthreads();

        const int NKB = H_ / KB;  // 64
        for (int kb = 0; kb < NKB; kb++) {
            const int cur = kb & 1;
            float4 nar0, nar1, nbr0, nbr1;
            const bool have_next = (kb < NKB - 1);
            if (have_next) {
                const int ko = (kb + 1) * KB;
                nar0 = *(const float4*)(Abase0 + ko);
                nar1 = *(const float4*)(Abase1 + ko);
                nbr0 = *(const float4*)(W2 + (size_t)(ko + b_row0) * H_ + n0 + b_c4 * 4);
                nbr1 = *(const float4*)(W2 + (size_t)(ko + b_row1) * H_ + n0 + b_c4 * 4);
            }

#pragma unroll
            for (int ks = 0; ks < KB; ks += 8) {
                uint32_t a[2][4];
#pragma unroll
                for (int mf = 0; mf < 2; mf++) {
                    const uint32_t* ap =
                        &As[cur][(rbase + mf * 16) * AS_STRIDE + ks + kq];
                    a[mf][0] = ap[0];
                    a[mf][1] = ap[8 * AS_STRIDE];
                    a[mf][2] = ap[4];
                    a[mf][3] = ap[8 * AS_STRIDE + 4];
                }
#pragma unroll
                for (int nf = 0; nf < 8; nf++) {
                    uint32_t bb0 = Bs[cur][(ks + kq) * BS_STRIDE + nb + nf * 8];
                    uint32_t bb1 = Bs[cur][(ks + 4 + kq) * BS_STRIDE + nb + nf * 8];
                    mma_m16n8k8(acc[0][nf], a[0], bb0, bb1);
                    mma_m16n8k8(acc[1][nf], a[1], bb0, bb1);
                }
            }

            if (have_next) {
                const int nxt = cur ^ 1;
                uint32_t* pa0 = &As[nxt][a_row0 * AS_STRIDE + a_c4 * 4];
                pa0[0] = f2tf32(nar0.x); pa0[1] = f2tf32(nar0.y);
                pa0[2] = f2tf32(nar0.z); pa0[3] = f2tf32(nar0.w);
                uint32_t* pa1 = &As[nxt][a_row1 * AS_STRIDE + a_c4 * 4];
                pa1[0] = f2tf32(nar1.x); pa1[1] = f2tf32(nar1.y);
                pa1[2] = f2tf32(nar1.z); pa1[3] = f2tf32(nar1.w);
                uint32_t* pb0 = &Bs[nxt][b_row0 * BS_STRIDE + b_c4 * 4];
                pb0[0] = f2tf32(nbr0.x); pb0[1] = f2tf32(nbr0.y);
                pb0[2] = f2tf32(nbr0.z); pb0[3] = f2tf32(nbr0.w);
                uint32_t* pb1 = &Bs[nxt][b_row1 * BS_STRIDE + b_c4 * 4];
                pb1[0] = f2tf32(nbr1.x); pb1[1] = f2tf32(nbr1.y);
                pb1[2] = f2tf32(nbr1.z); pb1[3] = f2tf32(nbr1.w);
                __syncthreads();
            }
        }

        // Epilogue: energy = tanh(acc + u), partial = energy * v, per-row sum.
#pragma unroll
        for (int mf = 0; mf < 2; mf++) {
            float s0 = 0.f, s1 = 0.f;
#pragma unroll
            for (int nf = 0; nf < 8; nf++) {
                const int cl = warp_n * 64 + nf * 8 + (lane & 3) * 2;
                const float u0 = u_s[cl],   u1 = u_s[cl + 1];
                const float w0 = v_s[cl],   w1 = v_s[cl + 1];
                s0 += tanhf(acc[mf][nf][0] + u0) * w0;
                s0 += tanhf(acc[mf][nf][1] + u1) * w1;
                s1 += tanhf(acc[mf][nf][2] + u0) * w0;
                s1 += tanhf(acc[mf][nf][3] + u1) * w1;
            }
            s0 += __shfl_xor_sync(0xffffffffu, s0, 1);
            s0 += __shfl_xor_sync(0xffffffffu, s0, 2);
            s1 += __shfl_xor_sync(0xffffffffu, s1, 1);
            s1 += __shfl_xor_sync(0xffffffffu, s1, 2);
            if ((lane & 3) == 0) {
                atomicAdd(&row_acc[rbase + mf * 16], s0);
                atomicAdd(&row_acc[rbase + mf * 16 + 8], s1);
            }
        }
        __syncthreads();  // row_acc atomics done; safe to reuse u_s/v_s/As/Bs
    }

    if (tid < MT) g_logits[gr0 + tid] = row_acc[tid];
}

// ---------------------------------------------------------------------------
// Kernel 3: softmax over S per batch. 16 blocks x 256 threads, 8 vals/thread.
// ---------------------------------------------------------------------------
__global__ void softmax_kernel(float* __restrict__ out) {
    const int b = blockIdx.x;
    const int tid = threadIdx.x;
    __shared__ float red[8];

    float vals[8];
    float m = -1e30f;
#pragma unroll
    for (int i = 0; i < 8; i++) {
        vals[i] = g_logits[b * S_ + tid + i * 256];
        m = fmaxf(m, vals[i]);
    }
#pragma unroll
    for (int o = 16; o; o >>= 1) m = fmaxf(m, __shfl_xor_sync(0xffffffffu, m, o));
    if ((tid & 31) == 0) red[tid >> 5] = m;
    __syncthreads();
    if (tid == 0) {
        float t = red[0];
#pragma unroll
        for (int i = 1; i < 8; i++) t = fmaxf(t, red[i]);
        red[0] = t;
    }
    __syncthreads();
    m = red[0];
    __syncthreads();  // everyone has m before red[] is reused

    float s = 0.f;
#pragma unroll
    for (int i = 0; i < 8; i++) {
        vals[i] = expf(vals[i] - m);
        s += vals[i];
    }
#pragma unroll
    for (int o = 16; o; o >>= 1) s += __shfl_xor_sync(0xffffffffu, s, o);
    if ((tid & 31) == 0) red[tid >> 5] = s;
    __syncthreads();
    if (tid == 0) {
        float t = 0.f;
#pragma unroll
        for (int i = 0; i < 8; i++) t += red[i];
        red[0] = t;
    }
    __syncthreads();
    const float inv = 1.0f / red[0];
#pragma unroll
    for (int i = 0; i < 8; i++)
        out[b * S_ + tid + i * 256] = vals[i] * inv;
}

// ---------------------------------------------------------------------------
// Launch
// ---------------------------------------------------------------------------
extern "C" void kernel_launch(void* const* d_in, const int* in_sizes, int n_in,
                              void* d_out, int out_size) {
    const float* hidden = (const float*)d_in[0];  // (16, 1024)
    const float* enc    = (const float*)d_in[1];  // (16, 2048, 1024)
    const float* W      = (const float*)d_in[2];  // (2048, 1024)
    const float* bias   = (const float*)d_in[3];  // (1024,)
    const float* v      = (const float*)d_in[4];  // (1024,)
    float* out = (float*)d_out;                   // (16, 2048)

    u_kernel<<<dim3(16, 4), 256>>>(hidden, W, bias);
    fused_kernel<<<(B_ * S_) / MT, 256>>>(enc, W, v);
    softmax_kernel<<<B_, 256>>>(out);
}

// round 4
// speedup vs baseline: 1.0482x; 1.0482x over previous
#include <cuda_runtime.h>
#include <cstdint>
#include <cstddef>

#define B_  16
#define S_  2048
#define H_  1024

// Scratch (static device memory — no allocation).
__device__ float g_u[B_ * H_];        // hid_part + bias, per (b, n)
__device__ float g_logits[B_ * S_];   // attention logits before softmax

// ---------------------------------------------------------------------------
// Helpers
// ---------------------------------------------------------------------------
__device__ __forceinline__ uint32_t f2tf32(float x) {
    uint32_t r;
    asm("cvt.rna.tf32.f32 %0, %1;" : "=r"(r) : "f"(x));
    return r;
}

__device__ __forceinline__ float tanh_fast(float x) {
    float y;
    asm("tanh.approx.f32 %0, %1;" : "=f"(y) : "f"(x));
    return y;
}

__device__ __forceinline__ void mma_m16n8k8(float* c, const uint32_t* a,
                                            uint32_t b0, uint32_t b1) {
    asm volatile(
        "mma.sync.aligned.m16n8k8.row.col.f32.tf32.tf32.f32 "
        "{%0,%1,%2,%3}, {%4,%5,%6,%7}, {%8,%9}, {%0,%1,%2,%3};\n"
        : "+f"(c[0]), "+f"(c[1]), "+f"(c[2]), "+f"(c[3])
        : "r"(a[0]), "r"(a[1]), "r"(a[2]), "r"(a[3]), "r"(b0), "r"(b1));
}

// ---------------------------------------------------------------------------
// Kernel 1: u[b][n] = sum_k hidden[b][k] * W_attn[k][n] + b_attn[n]
// grid (16, 8), 512 threads: 128 n per block, 4-way K split per n.
// ---------------------------------------------------------------------------
__global__ __launch_bounds__(512)
void u_kernel(const float* __restrict__ hidden,
              const float* __restrict__ W,
              const float* __restrict__ bias) {
    __shared__ float part[4][128];
    const int tid = threadIdx.x;
    const int b   = blockIdx.x;
    const int nl  = tid & 127;
    const int ks  = tid >> 7;                 // 0..3, each covers 256 k
    const int n   = blockIdx.y * 128 + nl;
    const float* h = hidden + b * H_ + ks * 256;
    const float* w = W + (size_t)(ks * 256) * H_ + n;
    float acc = 0.f;
#pragma unroll 8
    for (int k = 0; k < 256; k++)
        acc = fmaf(h[k], w[(size_t)k * H_], acc);
    part[ks][nl] = acc;
    __syncthreads();
    if (ks == 0)
        g_u[b * H_ + n] =
            part[0][nl] + part[1][nl] + part[2][nl] + part[3][nl] + bias[n];
}

// ---------------------------------------------------------------------------
// Kernel 2: fused enc@W2 (tf32 MMA) + tanh(.+u) + dot(v) -> logits
// Tile: M=128 rows of flattened (b*S+s), N-chunks of 128 over H, K=1024.
// 256 threads = 8 warps in a 4(m) x 2(n) grid; warp tile 32x64.
// B tile stored n-PERMUTED in smem: value (k, c) lives at [k][perm(c)],
// perm(c) = (c&7)*16 + (c>>3), so a thread's 8 B-frag values (n = nb+8*nf,
// nf=0..7) are contiguous -> 2x LDS.128 per k-row. Row stride 132 words
// gives conflict-free 8-lane phases for the LDS.128s.
// ---------------------------------------------------------------------------
#define KB 16
#define MT 128
#define NT 128
#define AS_STRIDE 20    // KB + 4  -> conflict-free A frag reads
#define BS_STRIDE 132   // words per B row (16B-aligned, phase-conflict-free)

__global__ __launch_bounds__(256, 2)
void fused_kernel(const float* __restrict__ enc,
                  const float* __restrict__ Wfull,
                  const float* __restrict__ v) {
    const float* W2 = Wfull + (size_t)H_ * H_;

    __shared__ __align__(16) uint32_t As[2][MT * AS_STRIDE];  // 20 KB
    __shared__ __align__(16) uint32_t Bs[2][KB * BS_STRIDE];  // 16.5 KB
    __shared__ float u_s[NT];
    __shared__ float v_s[NT];
    __shared__ float row_acc[MT];

    const int tid  = threadIdx.x;
    const int lane = tid & 31;
    const int wid  = tid >> 5;
    const int warp_m = wid & 3;   // 0..3 -> 32-row slab
    const int warp_n = wid >> 2;  // 0..1 -> 64-col slab
    const int gr0 = blockIdx.x * MT;        // global row base (b*S + s)
    const int b   = gr0 >> 11;              // S = 2048

    if (tid < MT) row_acc[tid] = 0.f;

    // Global->smem load mapping (float4 granularity).
    const int a_row0 = tid >> 2;
    const int a_c4   = tid & 3;
    const int a_row1 = a_row0 + 64;
    const int b_row0 = tid >> 5;
    const int b_c4   = tid & 31;
    const int b_row1 = b_row0 + 8;

    // Permuted B write columns for this thread's float4 (c = b_c4*4 + i).
    int pc[4];
#pragma unroll
    for (int i = 0; i < 4; i++) {
        const int c = b_c4 * 4 + i;
        pc[i] = (c & 7) * 16 + (c >> 3);
    }

    const float* Abase0 = enc + (size_t)(gr0 + a_row0) * H_ + a_c4 * 4;
    const float* Abase1 = enc + (size_t)(gr0 + a_row1) * H_ + a_c4 * 4;

    const int rbase = warp_m * 32 + (lane >> 2);  // C-frag row (mf=0, half 0)
    const int kq    = lane & 3;
    // Permuted B read base: thread's frag values at perm = (lane>>2)*16 + warp_n*8 + nf
    const int cbase = (lane >> 2) * 16 + warp_n * 8;

    for (int n0 = 0; n0 < H_; n0 += NT) {
        if (tid < NT)            u_s[tid]       = g_u[b * H_ + n0 + tid];
        else if (tid < 2 * NT)   v_s[tid - NT]  = v[n0 + tid - NT];

        float acc[2][8][4];
#pragma unroll
        for (int mf = 0; mf < 2; mf++)
#pragma unroll
            for (int nf = 0; nf < 8; nf++)
#pragma unroll
                for (int i = 0; i < 4; i++) acc[mf][nf][i] = 0.f;

        // Preload k-block 0 into buffer 0.
        {
            float4 ar0 = *(const float4*)(Abase0);
            float4 ar1 = *(const float4*)(Abase1);
            float4 br0 = *(const float4*)(W2 + (size_t)b_row0 * H_ + n0 + b_c4 * 4);
            float4 br1 = *(const float4*)(W2 + (size_t)b_row1 * H_ + n0 + b_c4 * 4);
            uint32_t* pa0 = &As[0][a_row0 * AS_STRIDE + a_c4 * 4];
            pa0[0] = f2tf32(ar0.x); pa0[1] = f2tf32(ar0.y);
            pa0[2] = f2tf32(ar0.z); pa0[3] = f2tf32(ar0.w);
            uint32_t* pa1 = &As[0][a_row1 * AS_STRIDE + a_c4 * 4];
            pa1[0] = f2tf32(ar1.x); pa1[1] = f2tf32(ar1.y);
            pa1[2] = f2tf32(ar1.z); pa1[3] = f2tf32(ar1.w);
            uint32_t* pb0 = &Bs[0][b_row0 * BS_STRIDE];
            pb0[pc[0]] = f2tf32(br0.x); pb0[pc[1]] = f2tf32(br0.y);
            pb0[pc[2]] = f2tf32(br0.z); pb0[pc[3]] = f2tf32(br0.w);
            uint32_t* pb1 = &Bs[0][b_row1 * BS_STRIDE];
            pb1[pc[0]] = f2tf32(br1.x); pb1[pc[1]] = f2tf32(br1.y);
            pb1[pc[2]] = f2tf32(br1.z); pb1[pc[3]] = f2tf32(br1.w);
        }
        __syncthreads();

        const int NKB = H_ / KB;  // 64
        for (int kb = 0; kb < NKB; kb++) {
            const int cur = kb & 1;
            float4 nar0, nar1, nbr0, nbr1;
            const bool have_next = (kb < NKB - 1);
            if (have_next) {
                const int ko = (kb + 1) * KB;
                nar0 = *(const float4*)(Abase0 + ko);
                nar1 = *(const float4*)(Abase1 + ko);
                nbr0 = *(const float4*)(W2 + (size_t)(ko + b_row0) * H_ + n0 + b_c4 * 4);
                nbr1 = *(const float4*)(W2 + (size_t)(ko + b_row1) * H_ + n0 + b_c4 * 4);
            }

#pragma unroll
            for (int ks = 0; ks < KB; ks += 8) {
                uint32_t a[2][4];
#pragma unroll
                for (int mf = 0; mf < 2; mf++) {
                    const uint32_t* ap =
                        &As[cur][(rbase + mf * 16) * AS_STRIDE + ks + kq];
                    a[mf][0] = ap[0];
                    a[mf][1] = ap[8 * AS_STRIDE];
                    a[mf][2] = ap[4];
                    a[mf][3] = ap[8 * AS_STRIDE + 4];
                }
                // Vectorized B-frag loads: rows k0, k0+4; 8 contiguous vals each.
                const int k0 = ks + kq;
                const uint32_t* p0 = &Bs[cur][k0 * BS_STRIDE + cbase];
                const uint32_t* p1 = &Bs[cur][(k0 + 4) * BS_STRIDE + cbase];
                const uint4 q00 = *(const uint4*)(p0);
                const uint4 q01 = *(const uint4*)(p0 + 4);
                const uint4 q10 = *(const uint4*)(p1);
                const uint4 q11 = *(const uint4*)(p1 + 4);
                const uint32_t bb0[8] = {q00.x, q00.y, q00.z, q00.w,
                                         q01.x, q01.y, q01.z, q01.w};
                const uint32_t bb1[8] = {q10.x, q10.y, q10.z, q10.w,
                                         q11.x, q11.y, q11.z, q11.w};
#pragma unroll
                for (int nf = 0; nf < 8; nf++) {
                    mma_m16n8k8(acc[0][nf], a[0], bb0[nf], bb1[nf]);
                    mma_m16n8k8(acc[1][nf], a[1], bb0[nf], bb1[nf]);
                }
            }

            if (have_next) {
                const int nxt = cur ^ 1;
                uint32_t* pa0 = &As[nxt][a_row0 * AS_STRIDE + a_c4 * 4];
                pa0[0] = f2tf32(nar0.x); pa0[1] = f2tf32(nar0.y);
                pa0[2] = f2tf32(nar0.z); pa0[3] = f2tf32(nar0.w);
                uint32_t* pa1 = &As[nxt][a_row1 * AS_STRIDE + a_c4 * 4];
                pa1[0] = f2tf32(nar1.x); pa1[1] = f2tf32(nar1.y);
                pa1[2] = f2tf32(nar1.z); pa1[3] = f2tf32(nar1.w);
                uint32_t* pb0 = &Bs[nxt][b_row0 * BS_STRIDE];
                pb0[pc[0]] = f2tf32(nbr0.x); pb0[pc[1]] = f2tf32(nbr0.y);
                pb0[pc[2]] = f2tf32(nbr0.z); pb0[pc[3]] = f2tf32(nbr0.w);
                uint32_t* pb1 = &Bs[nxt][b_row1 * BS_STRIDE];
                pb1[pc[0]] = f2tf32(nbr1.x); pb1[pc[1]] = f2tf32(nbr1.y);
                pb1[pc[2]] = f2tf32(nbr1.z); pb1[pc[3]] = f2tf32(nbr1.w);
                __syncthreads();
            }
        }

        // Epilogue: energy = tanh(acc + u), partial = energy * v, per-row sum.
#pragma unroll
        for (int mf = 0; mf < 2; mf++) {
            float s0 = 0.f, s1 = 0.f;
#pragma unroll
            for (int nf = 0; nf < 8; nf++) {
                const int cl = warp_n * 64 + nf * 8 + (lane & 3) * 2;
                const float u0 = u_s[cl],   u1 = u_s[cl + 1];
                const float w0 = v_s[cl],   w1 = v_s[cl + 1];
                s0 += tanh_fast(acc[mf][nf][0] + u0) * w0;
                s0 += tanh_fast(acc[mf][nf][1] + u1) * w1;
                s1 += tanh_fast(acc[mf][nf][2] + u0) * w0;
                s1 += tanh_fast(acc[mf][nf][3] + u1) * w1;
            }
            s0 += __shfl_xor_sync(0xffffffffu, s0, 1);
            s0 += __shfl_xor_sync(0xffffffffu, s0, 2);
            s1 += __shfl_xor_sync(0xffffffffu, s1, 1);
            s1 += __shfl_xor_sync(0xffffffffu, s1, 2);
            if ((lane & 3) == 0) {
                atomicAdd(&row_acc[rbase + mf * 16], s0);
                atomicAdd(&row_acc[rbase + mf * 16 + 8], s1);
            }
        }
        __syncthreads();  // row_acc atomics done; safe to reuse u_s/v_s/As/Bs
    }

    if (tid < MT) g_logits[gr0 + tid] = row_acc[tid];
}

// ---------------------------------------------------------------------------
// Kernel 3: softmax over S per batch. 16 blocks x 256 threads, 8 vals/thread.
// ---------------------------------------------------------------------------
__global__ void softmax_kernel(float* __restrict__ out) {
    const int b = blockIdx.x;
    const int tid = threadIdx.x;
    __shared__ float red[8];

    float vals[8];
    float m = -1e30f;
#pragma unroll
    for (int i = 0; i < 8; i++) {
        vals[i] = g_logits[b * S_ + tid + i * 256];
        m = fmaxf(m, vals[i]);
    }
#pragma unroll
    for (int o = 16; o; o >>= 1) m = fmaxf(m, __shfl_xor_sync(0xffffffffu, m, o));
    if ((tid & 31) == 0) red[tid >> 5] = m;
    __syncthreads();
    if (tid == 0) {
        float t = red[0];
#pragma unroll
        for (int i = 1; i < 8; i++) t = fmaxf(t, red[i]);
        red[0] = t;
    }
    __syncthreads();
    m = red[0];
    __syncthreads();

    float s = 0.f;
#pragma unroll
    for (int i = 0; i < 8; i++) {
        vals[i] = expf(vals[i] - m);
        s += vals[i];
    }
#pragma unroll
    for (int o = 16; o; o >>= 1) s += __shfl_xor_sync(0xffffffffu, s, o);
    if ((tid & 31) == 0) red[tid >> 5] = s;
    __syncthreads();
    if (tid == 0) {
        float t = 0.f;
#pragma unroll
        for (int i = 0; i < 8; i++) t += red[i];
        red[0] = t;
    }
    __syncthreads();
    const float inv = 1.0f / red[0];
#pragma unroll
    for (int i = 0; i < 8; i++)
        out[b * S_ + tid + i * 256] = vals[i] * inv;
}

// ---------------------------------------------------------------------------
// Launch
// ---------------------------------------------------------------------------
extern "C" void kernel_launch(void* const* d_in, const int* in_sizes, int n_in,
                              void* d_out, int out_size) {
    const float* hidden = (const float*)d_in[0];  // (16, 1024)
    const float* enc    = (const float*)d_in[1];  // (16, 2048, 1024)
    const float* W      = (const float*)d_in[2];  // (2048, 1024)
    const float* bias   = (const float*)d_in[3];  // (1024,)
    const float* v      = (const float*)d_in[4];  // (1024,)
    float* out = (float*)d_out;                   // (16, 2048)

    u_kernel<<<dim3(16, 8), 512>>>(hidden, W, bias);
    fused_kernel<<<(B_ * S_) / MT, 256>>>(enc, W, v);
    softmax_kernel<<<B_, 256>>>(out);
}

// round 14
// speedup vs baseline: 2.0047x; 1.9125x over previous
#include <cuda_runtime.h>
#include <cuda_fp16.h>
#include <cstdint>
#include <cstddef>

#define B_  16
#define S_  2048
#define H_  1024

// Static device scratch (no allocation). 16B-aligned for vector access.
__device__ __align__(16) float    g_u[B_ * H_];                 // hid_part + bias
__device__ __align__(16) float    g_logits[B_ * S_];            // logits before softmax
__device__ __align__(16) __half   g_ench[(size_t)B_ * S_ * H_]; // enc as half (67 MB)
__device__ __align__(16) uint32_t g_W2p[(H_ / 2) * H_];         // [kp][n] = half2(W2[2kp][n], W2[2kp+1][n])

// ---------------------------------------------------------------------------
// Helpers
// ---------------------------------------------------------------------------
__device__ __forceinline__ float tanh_fast(float x) {
    float y;
    asm("tanh.approx.f32 %0, %1;" : "=f"(y) : "f"(x));
    return y;
}

__device__ __forceinline__ void mma_f16_16816(float* c, const uint32_t* a,
                                              uint32_t b0, uint32_t b1) {
    asm volatile(
        "mma.sync.aligned.m16n8k16.row.col.f32.f16.f16.f32 "
        "{%0,%1,%2,%3}, {%4,%5,%6,%7}, {%8,%9}, {%0,%1,%2,%3};\n"
        : "+f"(c[0]), "+f"(c[1]), "+f"(c[2]), "+f"(c[3])
        : "r"(a[0]), "r"(a[1]), "r"(a[2]), "r"(a[3]), "r"(b0), "r"(b1));
}

// ---------------------------------------------------------------------------
// Pre-kernel 1: enc (fp32) -> g_ench (half). 33.55M elements, 4 per thread.
// ---------------------------------------------------------------------------
__global__ __launch_bounds__(256)
void enc2h_kernel(const float* __restrict__ enc) {
    const size_t i = ((size_t)blockIdx.x * 256 + threadIdx.x) * 4;
    const float4 f = *(const float4*)(enc + i);
    const __half2 lo = __floats2half2_rn(f.x, f.y);
    const __half2 hi = __floats2half2_rn(f.z, f.w);
    uint2 o;
    o.x = *(const uint32_t*)&lo;
    o.y = *(const uint32_t*)&hi;
    *(uint2*)(g_ench + i) = o;
}

// ---------------------------------------------------------------------------
// Pre-kernel 2: pack W2 rows k-pairwise into half2 words, [kp][n].
// grid (4, 512), 256 threads.
// ---------------------------------------------------------------------------
__global__ __launch_bounds__(256)
void w2pack_kernel(const float* __restrict__ Wfull) {
    const float* W2 = Wfull + (size_t)H_ * H_;
    const int n  = blockIdx.x * 256 + threadIdx.x;
    const int kp = blockIdx.y;
    const float a = W2[(size_t)(2 * kp) * H_ + n];
    const float b = W2[(size_t)(2 * kp + 1) * H_ + n];
    const __half2 p = __floats2half2_rn(a, b);
    g_W2p[(size_t)kp * H_ + n] = *(const uint32_t*)&p;
}

// ---------------------------------------------------------------------------
// Kernel: u[b][n] = hidden[b] . W1[:,n] + bias[n].  8-way K split.
// ---------------------------------------------------------------------------
__global__ __launch_bounds__(1024)
void u_kernel(const float* __restrict__ hidden,
              const float* __restrict__ W,
              const float* __restrict__ bias) {
    __shared__ float part[8][128];
    const int tid = threadIdx.x;
    const int b   = blockIdx.x;
    const int nl  = tid & 127;
    const int ks  = tid >> 7;
    const int n   = blockIdx.y * 128 + nl;
    const float* h = hidden + b * H_ + ks * 128;
    const float* w = W + (size_t)(ks * 128) * H_ + n;
    float acc = 0.f;
#pragma unroll 8
    for (int k = 0; k < 128; k++)
        acc = fmaf(h[k], w[(size_t)k * H_], acc);
    part[ks][nl] = acc;
    __syncthreads();
    if (ks == 0) {
        float s = bias[n];
#pragma unroll
        for (int i = 0; i < 8; i++) s += part[i][nl];
        g_u[b * H_ + n] = s;
    }
}

// ---------------------------------------------------------------------------
// Fused kernel: enc@W2 via fp16 m16n8k16 MMA + tanh + v-dot -> logits.
// CTA: M=128 flattened rows, 8 N-chunks of 128, K=1024 in KB=16 blocks.
// 8 warps in 4(m) x 2(n); warp tile 32 x 64.
// B global read for chunk c, k-block kb: rows kp = kb*8 + b_kp (0..511),
// cols n = c*128 + b_n4.  (Round-13 fault: c*8 was in the row term and the
// c*128 column offset was missing -> OOB reads past g_W2p.)
// ---------------------------------------------------------------------------
#define KB 16
#define MT 128
#define NT 128
#define AW 12     // A words per row
#define BW 132    // B words per kp row

__global__ __launch_bounds__(256, 2)
void fused_fp16_kernel(const float* __restrict__ v) {
    __shared__ __align__(16) uint32_t As[2][MT * AW];   // 12 KB
    __shared__ __align__(16) uint32_t Bs[2][8 * BW];    // 8.25 KB
    __shared__ float u_s[NT];
    __shared__ float v_s[NT];
    __shared__ float row_acc[MT];

    const int tid  = threadIdx.x;
    const int lane = tid & 31;
    const int wid  = tid >> 5;
    const int warp_m = wid & 3;
    const int warp_n = wid >> 2;
    const int gr0 = blockIdx.x * MT;
    const int b   = gr0 >> 11;

    if (tid < MT) row_acc[tid] = 0.f;

    // Fill mappings.
    const int a_row = tid >> 1;          // 0..127
    const int a_hb  = tid & 1;           // which 8-half block of the 16
    const int b_kp  = tid >> 5;          // 0..7
    const int b_n4  = (tid & 31) * 4;    // n base for 4 words
    int pc[4];
#pragma unroll
    for (int i = 0; i < 4; i++) {
        const int n = b_n4 + i;
        pc[i] = (n & 7) * 16 + (n >> 3);
    }

    const __half* Ag = g_ench + (size_t)(gr0 + a_row) * H_ + a_hb * 8;

    // Fragment read indices.
    const int gid = lane >> 2;           // 0..7
    const int q   = lane & 3;            // 0..3
    const int rbase = warp_m * 32 + gid; // C-frag row (mf=0, half 0)
    const int cbase = gid * 16 + warp_n * 8;

    for (int n0 = 0; n0 < H_; n0 += NT) {
        const int c = n0 >> 7;   // chunk index 0..7
        if (tid < NT)            u_s[tid]      = g_u[b * H_ + n0 + tid];
        else if (tid < 2 * NT)   v_s[tid - NT] = v[n0 + tid - NT];

        float acc[2][8][4];
#pragma unroll
        for (int mf = 0; mf < 2; mf++)
#pragma unroll
            for (int nf = 0; nf < 8; nf++)
#pragma unroll
                for (int i = 0; i < 4; i++) acc[mf][nf][i] = 0.f;

        // Preload k-block 0 into buffer 0. B: rows kp = b_kp, cols c*128 + b_n4.
        {
            const uint4 av = *(const uint4*)(Ag);
            const uint4 bv = *(const uint4*)(g_W2p + (size_t)b_kp * H_ + c * 128 + b_n4);
            *(uint4*)&As[0][a_row * AW + a_hb * 4] = av;
            Bs[0][b_kp * BW + pc[0]] = bv.x;
            Bs[0][b_kp * BW + pc[1]] = bv.y;
            Bs[0][b_kp * BW + pc[2]] = bv.z;
            Bs[0][b_kp * BW + pc[3]] = bv.w;
        }
        __syncthreads();

        const int NKB = H_ / KB;  // 64
        for (int kb = 0; kb < NKB; kb++) {
            const int cur = kb & 1;
            uint4 nav, nbv;
            const bool have_next = (kb < NKB - 1);
            if (have_next) {
                const int ko = (kb + 1) * KB;
                nav = *(const uint4*)(Ag + ko);
                // B: rows kp = (kb+1)*8 + b_kp  (= (ko>>1) + b_kp <= 511),
                //    cols n = c*128 + b_n4.
                nbv = *(const uint4*)(g_W2p +
                        (size_t)((ko >> 1) + b_kp) * H_ + c * 128 + b_n4);
            }

            // A fragments (one k16 step): words [r][q], [r+8][q], [r][q+4], [r+8][q+4]
            uint32_t a[2][4];
#pragma unroll
            for (int mf = 0; mf < 2; mf++) {
                const uint32_t* ap = &As[cur][(rbase + mf * 16) * AW + q];
                a[mf][0] = ap[0];
                a[mf][1] = ap[8 * AW];
                a[mf][2] = ap[4];
                a[mf][3] = ap[8 * AW + 4];
            }
            // B fragments: b0 rows kp=q, b1 rows kp=q+4; 8 consecutive perm cols.
            const uint32_t* p0 = &Bs[cur][q * BW + cbase];
            const uint32_t* p1 = &Bs[cur][(q + 4) * BW + cbase];
            const uint4 q00 = *(const uint4*)(p0);
            const uint4 q01 = *(const uint4*)(p0 + 4);
            const uint4 q10 = *(const uint4*)(p1);
            const uint4 q11 = *(const uint4*)(p1 + 4);
            const uint32_t bb0[8] = {q00.x, q00.y, q00.z, q00.w,
                                     q01.x, q01.y, q01.z, q01.w};
            const uint32_t bb1[8] = {q10.x, q10.y, q10.z, q10.w,
                                     q11.x, q11.y, q11.z, q11.w};
#pragma unroll
            for (int nf = 0; nf < 8; nf++) {
                mma_f16_16816(acc[0][nf], a[0], bb0[nf], bb1[nf]);
                mma_f16_16816(acc[1][nf], a[1], bb0[nf], bb1[nf]);
            }

            if (have_next) {
                const int nxt = cur ^ 1;
                *(uint4*)&As[nxt][a_row * AW + a_hb * 4] = nav;
                Bs[nxt][b_kp * BW + pc[0]] = nbv.x;
                Bs[nxt][b_kp * BW + pc[1]] = nbv.y;
                Bs[nxt][b_kp * BW + pc[2]] = nbv.z;
                Bs[nxt][b_kp * BW + pc[3]] = nbv.w;
                __syncthreads();
            }
        }

        // Epilogue: tanh(acc + u) . v, per-row partial sums.
#pragma unroll
        for (int mf = 0; mf < 2; mf++) {
            float s0 = 0.f, s1 = 0.f;
#pragma unroll
            for (int nf = 0; nf < 8; nf++) {
                const int cl = warp_n * 64 + nf * 8 + q * 2;
                const float u0 = u_s[cl],   u1 = u_s[cl + 1];
                const float w0 = v_s[cl],   w1 = v_s[cl + 1];
                s0 += tanh_fast(acc[mf][nf][0] + u0) * w0;
                s0 += tanh_fast(acc[mf][nf][1] + u1) * w1;
                s1 += tanh_fast(acc[mf][nf][2] + u0) * w0;
                s1 += tanh_fast(acc[mf][nf][3] + u1) * w1;
            }
            s0 += __shfl_xor_sync(0xffffffffu, s0, 1);
            s0 += __shfl_xor_sync(0xffffffffu, s0, 2);
            s1 += __shfl_xor_sync(0xffffffffu, s1, 1);
            s1 += __shfl_xor_sync(0xffffffffu, s1, 2);
            if (q == 0) {
                atomicAdd(&row_acc[rbase + mf * 16], s0);
                atomicAdd(&row_acc[rbase + mf * 16 + 8], s1);
            }
        }
        __syncthreads();
    }

    if (tid < MT) g_logits[gr0 + tid] = row_acc[tid];
}

// ---------------------------------------------------------------------------
// Softmax over S per batch.
// ---------------------------------------------------------------------------
__global__ void softmax_kernel(float* __restrict__ out) {
    const int b = blockIdx.x;
    const int tid = threadIdx.x;
    __shared__ float red[8];

    float vals[8];
    float m = -1e30f;
#pragma unroll
    for (int i = 0; i < 8; i++) {
        vals[i] = g_logits[b * S_ + tid + i * 256];
        m = fmaxf(m, vals[i]);
    }
#pragma unroll
    for (int o = 16; o; o >>= 1) m = fmaxf(m, __shfl_xor_sync(0xffffffffu, m, o));
    if ((tid & 31) == 0) red[tid >> 5] = m;
    __syncthreads();
    if (tid == 0) {
        float t = red[0];
#pragma unroll
        for (int i = 1; i < 8; i++) t = fmaxf(t, red[i]);
        red[0] = t;
    }
    __syncthreads();
    m = red[0];
    __syncthreads();

    float s = 0.f;
#pragma unroll
    for (int i = 0; i < 8; i++) {
        vals[i] = expf(vals[i] - m);
        s += vals[i];
    }
#pragma unroll
    for (int o = 16; o; o >>= 1) s += __shfl_xor_sync(0xffffffffu, s, o);
    if ((tid & 31) == 0) red[tid >> 5] = s;
    __syncthreads();
    if (tid == 0) {
        float t = 0.f;
#pragma unroll
        for (int i = 0; i < 8; i++) t += red[i];
        red[0] = t;
    }
    __syncthreads();
    const float inv = 1.0f / red[0];
#pragma unroll
    for (int i = 0; i < 8; i++)
        out[b * S_ + tid + i * 256] = vals[i] * inv;
}

// ---------------------------------------------------------------------------
// Launch
// ---------------------------------------------------------------------------
extern "C" void kernel_launch(void* const* d_in, const int* in_sizes, int n_in,
                              void* d_out, int out_size) {
    const float* hidden = (const float*)d_in[0];  // (16, 1024)
    const float* enc    = (const float*)d_in[1];  // (16, 2048, 1024)
    const float* W      = (const float*)d_in[2];  // (2048, 1024)
    const float* bias   = (const float*)d_in[3];  // (1024,)
    const float* v      = (const float*)d_in[4];  // (1024,)
    float* out = (float*)d_out;                   // (16, 2048)

    enc2h_kernel<<<(B_ * S_ * H_) / (256 * 4), 256>>>(enc);
    w2pack_kernel<<<dim3(H_ / 256, H_ / 2), 256>>>(W);
    u_kernel<<<dim3(16, 8), 1024>>>(hidden, W, bias);
    fused_fp16_kernel<<<(B_ * S_) / MT, 256>>>(v);
    softmax_kernel<<<B_, 256>>>(out);
}